// round 16
// baseline (speedup 1.0000x reference)
#include <cuda_runtime.h>
#include <cuda_bf16.h>
#include <math.h>
#include <stdint.h>

// Fixed dataset shapes
#define MAX_N 4096
#define MAX_C 50257
#define EDIM  512
#define NCB   197          // ceil(50257 / 256) class blocks
#define NSUB  4            // per-warp_n partial sums per class block

// ---------------- device scratch (no allocations allowed) ----------------
__device__ __nv_bfloat16 g_xb[MAX_N * EDIM];     // normalized x, bf16
__device__ __nv_bfloat16 g_wb[(size_t)MAX_C * EDIM]; // normalized W, bf16 (~51.5 MB)
__device__ int   g_label[MAX_N];
__device__ float g_tgt[MAX_N];
__device__ float g_partS[(size_t)NCB * NSUB * MAX_N];  // [cb*4+wn][row] partial sums
__device__ float g_rowloss[MAX_N];

// ---------------- PTX helpers (sm_80-class + base-sm_100 f32x2; no 'a' gating) --------
__device__ __forceinline__ uint32_t smem_u32(const void* p) {
    return (uint32_t)__cvta_generic_to_shared(p);
}
__device__ __forceinline__ void cp_async16(uint32_t saddr, const void* gaddr, int srcsz) {
    asm volatile("cp.async.cg.shared.global [%0], [%1], 16, %2;\n"
                 :: "r"(saddr), "l"(gaddr), "r"(srcsz) : "memory");
}
__device__ __forceinline__ void cp_commit() { asm volatile("cp.async.commit_group;\n" ::: "memory"); }
template <int n>
__device__ __forceinline__ void cp_wait_group() {
    asm volatile("cp.async.wait_group %0;\n" :: "n"(n) : "memory");
}
__device__ __forceinline__ void bar_sync_id(int id) {
    asm volatile("bar.sync %0, 288;" :: "r"(id) : "memory");
}
__device__ __forceinline__ void bar_arrive_id(int id) {
    asm volatile("bar.arrive %0, 288;" :: "r"(id) : "memory");
}
__device__ __forceinline__ void ldsm_x4(uint32_t& r0, uint32_t& r1, uint32_t& r2, uint32_t& r3,
                                        uint32_t addr) {
    asm volatile("ldmatrix.sync.aligned.m8n8.x4.shared.b16 {%0,%1,%2,%3}, [%4];"
                 : "=r"(r0), "=r"(r1), "=r"(r2), "=r"(r3) : "r"(addr));
}
__device__ __forceinline__ void mma16816(float* c, uint32_t a0, uint32_t a1, uint32_t a2,
                                         uint32_t a3, uint32_t b0, uint32_t b1) {
    asm volatile("mma.sync.aligned.m16n8k16.row.col.f32.bf16.bf16.f32 "
                 "{%0,%1,%2,%3}, {%4,%5,%6,%7}, {%8,%9}, {%0,%1,%2,%3};"
                 : "+f"(c[0]), "+f"(c[1]), "+f"(c[2]), "+f"(c[3])
                 : "r"(a0), "r"(a1), "r"(a2), "r"(a3), "r"(b0), "r"(b1));
}
__device__ __forceinline__ uint32_t sw128(uint32_t b) { return b ^ ((b >> 3) & 0x70); }

// packed f32x2 (PTX ISA 8.6, sm_100+ base feature)
__device__ __forceinline__ uint64_t f2pack(float x, float y) {
    uint64_t r;
    asm("mov.b64 %0, {%1, %2};" : "=l"(r) : "r"(__float_as_uint(x)), "r"(__float_as_uint(y)));
    return r;
}
__device__ __forceinline__ float f2sum(uint64_t v) {
    uint32_t a, b;
    asm("mov.b64 {%0, %1}, %2;" : "=r"(a), "=r"(b) : "l"(v));
    return __uint_as_float(a) + __uint_as_float(b);
}
__device__ __forceinline__ uint64_t fma2(uint64_t a, uint64_t b, uint64_t c) {
    uint64_t d;
    asm("fma.rn.f32x2 %0, %1, %2, %3;" : "=l"(d) : "l"(a), "l"(b), "l"(c));
    return d;
}
__device__ __forceinline__ uint64_t add2(uint64_t a, uint64_t b) {
    uint64_t d;
    asm("add.rn.f32x2 %0, %1, %2;" : "=l"(d) : "l"(a), "l"(b));
    return d;
}

// exp(v-1) deg-3 Taylor, coeffs e^-1 * {1, 1, 1/2, 1/6}.
#define EC0 3.6787944117144233e-1f
#define EC1 3.6787944117144233e-1f
#define EC2 1.8393972058572117e-1f
#define EC3 6.1313240195240389e-2f
__device__ __forceinline__ float expv3(float v) {
    float p = EC3;
    p = fmaf(p, v, EC2); p = fmaf(p, v, EC1); p = fmaf(p, v, EC0);
    return p;
}

// ---------------- normalization: fp32 src -> bf16 normalized rows (warp per row) ------
__global__ void k_norm_rows(const float* __restrict__ src, int nrows, int which) {
    __nv_bfloat16* dst = which ? g_wb : g_xb;
    int row = blockIdx.x * (blockDim.x >> 5) + (threadIdx.x >> 5);
    if (row >= nrows) return;
    int lane = threadIdx.x & 31;
    const float4* ip = reinterpret_cast<const float4*>(src) + (size_t)row * (EDIM >> 2);
    float4 v[4];
    float ss = 0.f;
    #pragma unroll
    for (int q = 0; q < 4; q++) {
        v[q] = ip[lane + 32 * q];
        ss += v[q].x * v[q].x + v[q].y * v[q].y + v[q].z * v[q].z + v[q].w * v[q].w;
    }
    #pragma unroll
    for (int m = 16; m; m >>= 1) ss += __shfl_xor_sync(0xffffffffu, ss, m);
    float scale = 1.f / fmaxf(sqrtf(ss), 1e-12f);
    __nv_bfloat162* op = reinterpret_cast<__nv_bfloat162*>(dst) + (size_t)row * (EDIM >> 1);
    #pragma unroll
    for (int q = 0; q < 4; q++) {
        int i = lane + 32 * q;
        op[2 * i]     = __floats2bfloat162_rn(v[q].x * scale, v[q].y * scale);
        op[2 * i + 1] = __floats2bfloat162_rn(v[q].z * scale, v[q].w * scale);
    }
}

// ---------------- label dtype detection (int32 vs int64 storage) ----------------
__global__ void k_prep_labels(const int* __restrict__ li, int N) {
    int any = 0;
    for (int i = threadIdx.x; i < (N >> 1); i += blockDim.x)
        if (li[2 * i + 1] != 0) any = 1;
    int is32 = __syncthreads_or(any);
    if (is32) { for (int i = threadIdx.x; i < N; i += blockDim.x) g_label[i] = li[i]; }
    else      { for (int i = threadIdx.x; i < N; i += blockDim.x) g_label[i] = li[2 * i]; }
}

// ---------------- target cosine per row (bf16 inputs, fp32 accumulate) ----------------
__global__ void k_target_dot() {
    int row = blockIdx.x;
    int lab = g_label[row];
    const __nv_bfloat162* a = reinterpret_cast<const __nv_bfloat162*>(g_xb) + (size_t)row * (EDIM >> 1);
    const __nv_bfloat162* b = reinterpret_cast<const __nv_bfloat162*>(g_wb) + (size_t)lab * (EDIM >> 1);
    float s = 0.f;
    for (int i = threadIdx.x; i < (EDIM >> 1); i += blockDim.x) {
        float2 u = __bfloat1622float2(a[i]);
        float2 v = __bfloat1622float2(b[i]);
        s += u.x * v.x + u.y * v.y;
    }
    __shared__ float red[4];
    #pragma unroll
    for (int m = 16; m; m >>= 1) s += __shfl_xor_sync(0xffffffffu, s, m);
    if ((threadIdx.x & 31) == 0) red[threadIdx.x >> 5] = s;
    __syncthreads();
    if (threadIdx.x == 0) g_tgt[row] = red[0] + red[1] + red[2] + red[3];
}

// ---------------- persistent warp-specialized bf16 HMMA GEMM + fused sum-exp ----------
// Grid 148 (1 CTA/SM). Block 288 = 8 compute warps (2m x 4n, 64x64 subtiles) + 1 loader.
// SMEM: A resident [8 chunks][128 rows][128B] = 128KB @0,
//       B ring 3 stages x [256 rows][128B] = 96KB @131072.
// Named barriers: full[s]=1+s, empty[s]=4+s (s=0..2), A_full=7, A_empty=8. Count=288.
#define SM_B    131072
#define SM_TOT  229376
#define NPERS   148

__global__ void __launch_bounds__(288, 1) k_lse_mma(int N, int C) {
    extern __shared__ __align__(128) char smem[];
    const uint32_t sb = smem_u32(smem);
    const int tid  = threadIdx.x;
    const int warp = tid >> 5;
    const int lane = tid & 31;

    const int nrb = N >> 7;
    const int ncb = (C + 255) >> 8;
    const int tot = nrb * ncb;
    int ts = (int)(((long long)blockIdx.x * tot) / NPERS);
    int te = (int)(((long long)(blockIdx.x + 1) * tot) / NPERS);

    if (warp == 8) {
        // ---------------- loader warp: owns ALL cp.async traffic ----------------
        int gj = 0;
        bool first = true;
        int t = ts;
        while (t < te) {
            int rb = t / ncb;
            int segEnd = min(te, (rb + 1) * ncb);
            int L = (segEnd - t) * 8;
            if (!first) bar_sync_id(8);                  // wait compute done with old A
            first = false;
            // stage A tile (128 rows x K=512 bf16, 8 SW128 chunks)
            {
                const __nv_bfloat16* ag = g_xb + ((size_t)rb * 128) * EDIM;
                for (int q = 0; q < 256; q++) {          // 8192 16B units / 32 lanes
                    int i = lane + q * 32;
                    int kc = i >> 10, jj = i & 1023;
                    int row = jj >> 3, s16 = jj & 7;
                    cp_async16(sb + kc * 16384 + sw128(row * 128 + s16 * 16),
                               ag + (size_t)row * EDIM + kc * 64 + s16 * 8, 16);
                }
            }
            cp_commit(); cp_wait_group<0>();
            bar_arrive_id(7);                            // A full
            for (int j = 0; j < L; j++, gj++) {
                int st = gj % 3;
                if (gj >= 3) bar_sync_id(4 + st);        // wait stage consumed
                int cb = (t + (j >> 3)) % ncb;
                int kb = j & 7;
                uint32_t bbase = sb + SM_B + st * 32768;
                const __nv_bfloat16* wbk = g_wb + (size_t)kb * 64;
                for (int q = 0; q < 64; q++) {           // 2048 16B units / 32 lanes
                    int i = lane + q * 32;
                    int row = i >> 3, s16 = i & 7;
                    int cls = cb * 256 + row;
                    int ok = (cls < C);
                    cp_async16(bbase + sw128(row * 128 + s16 * 16),
                               wbk + (size_t)(ok ? cls : 0) * EDIM + s16 * 8, ok ? 16 : 0);
                }
                cp_commit(); cp_wait_group<0>();
                bar_arrive_id(1 + st);                   // stage full
            }
            t = segEnd;
        }
    } else {
        // ---------------- compute warps 0-7: pure ldsm + mma + epilogue ----------------
        const int warp_m = warp >> 2;       // 0..1
        const int warp_n = warp & 3;        // 0..3
        const int lrow = (lane & 7) + ((lane >> 3) & 1) * 8;
        const int lkb  = ((lane >> 4) & 1) * 16;
        const int arow = warp_m * 64 + lrow;
        const int brow = warp_n * 64 + lrow;

        float acc[4][8][4];
        int gj = 0;
        int t = ts;
        while (t < te) {
            int rb = t / ncb;
            int segEnd = min(te, (rb + 1) * ncb);
            int L = (segEnd - t) * 8;
            bar_sync_id(7);                              // wait A staged
            for (int j = 0; j < L; j++, gj++) {
                int st = gj % 3;
                int kb = j & 7;
                bar_sync_id(1 + st);                     // wait stage full

                if (kb == 0) {
                    #pragma unroll
                    for (int mf = 0; mf < 4; mf++)
                        #pragma unroll
                        for (int nf = 0; nf < 8; nf++)
                            #pragma unroll
                            for (int q = 0; q < 4; q++) acc[mf][nf][q] = 0.f;
                }

                uint32_t abase = sb + kb * 16384;
                uint32_t bbase = sb + SM_B + st * 32768;
                #pragma unroll
                for (int kf = 0; kf < 4; kf++) {
                    uint32_t a[4][4];
                    #pragma unroll
                    for (int mf = 0; mf < 4; mf++)
                        ldsm_x4(a[mf][0], a[mf][1], a[mf][2], a[mf][3],
                                abase + sw128((arow + mf * 16) * 128 + kf * 32 + lkb));
                    uint32_t b[8][2];
                    #pragma unroll
                    for (int np = 0; np < 4; np++) {
                        uint32_t r0, r1, r2, r3;
                        ldsm_x4(r0, r1, r2, r3,
                                bbase + sw128((brow + np * 16) * 128 + kf * 32 + lkb));
                        b[np * 2][0] = r0; b[np * 2 + 1][0] = r1;
                        b[np * 2][1] = r2; b[np * 2 + 1][1] = r3;
                    }
                    #pragma unroll
                    for (int mf = 0; mf < 4; mf++)
                        #pragma unroll
                        for (int nf = 0; nf < 8; nf++)
                            mma16816(acc[mf][nf], a[mf][0], a[mf][1], a[mf][2], a[mf][3],
                                     b[nf][0], b[nf][1]);
                }
                bar_arrive_id(4 + st);                   // stage consumed (regs only below)

                if (kb == 7) {
                    // ---- barrier-free epilogue: per-warp_n partials straight to global ----
                    int ct = t + (j >> 3);
                    int cb = ct % ncb;
                    float rs[8];
                    const bool full = (cb * 256 + 256) <= C;
                    if (full) {
                        uint64_t c3 = f2pack(EC3, EC3), c2 = f2pack(EC2, EC2),
                                 c1 = f2pack(EC1, EC1), c0 = f2pack(EC0, EC0);
                        uint64_t rp[8];
                        #pragma unroll
                        for (int i = 0; i < 8; i++) rp[i] = 0;   // (0.0f, 0.0f)
                        #pragma unroll
                        for (int mf = 0; mf < 4; mf++) {
                            #pragma unroll
                            for (int nf = 0; nf < 8; nf++) {
                                float* c = acc[mf][nf];
                                #pragma unroll
                                for (int h = 0; h < 2; h++) {
                                    uint64_t v = f2pack(c[2 * h], c[2 * h + 1]);
                                    uint64_t p = c3;
                                    p = fma2(p, v, c2); p = fma2(p, v, c1); p = fma2(p, v, c0);
                                    rp[mf * 2 + h] = add2(rp[mf * 2 + h], p);
                                }
                            }
                        }
                        #pragma unroll
                        for (int i = 0; i < 8; i++) rs[i] = f2sum(rp[i]);
                    } else {
                        #pragma unroll
                        for (int i = 0; i < 8; i++) rs[i] = 0.f;
                        const int colb = cb * 256 + warp_n * 64 + (lane & 3) * 2;
                        #pragma unroll
                        for (int mf = 0; mf < 4; mf++)
                            #pragma unroll
                            for (int nf = 0; nf < 8; nf++) {
                                float* c = acc[mf][nf];
                                int cc = colb + nf * 8;
                                if (cc < C)     { rs[mf * 2] += expv3(c[0]); rs[mf * 2 + 1] += expv3(c[2]); }
                                if (cc + 1 < C) { rs[mf * 2] += expv3(c[1]); rs[mf * 2 + 1] += expv3(c[3]); }
                            }
                    }
                    #pragma unroll
                    for (int i = 0; i < 8; i++) {
                        rs[i] += __shfl_xor_sync(0xffffffffu, rs[i], 1);
                        rs[i] += __shfl_xor_sync(0xffffffffu, rs[i], 2);
                    }
                    if ((lane & 3) == 0) {
                        float* dst = g_partS + ((size_t)cb * NSUB + warp_n) * MAX_N + rb * 128;
                        #pragma unroll
                        for (int mf = 0; mf < 4; mf++) {
                            int r = warp_m * 64 + mf * 16 + (lane >> 2);
                            dst[r]     = rs[mf * 2];
                            dst[r + 8] = rs[mf * 2 + 1];
                        }
                    }
                }
            }
            bar_arrive_id(8);                            // done with this A tile
            t = segEnd;
        }
    }
}

// ---------------- combine partials (cooperative, coalesced) + margin patch ------------
__global__ void k_combine(int N, int nn, float cosM, float sinM) {
    int r0 = blockIdx.x * 32;
    int lane = threadIdx.x & 31;
    int w = threadIdx.x >> 5;
    const float* __restrict__ p = g_partS + r0 + lane;
    float s = 0.f;
    int sIdx = w;
    #pragma unroll 4
    for (; sIdx < nn; sIdx += 8) s += p[(size_t)sIdx * MAX_N];
    __shared__ float sm[8][32];
    sm[w][lane] = s;
    __syncthreads();
    if (w == 0) {
        float S = 0.f;
        #pragma unroll
        for (int i = 0; i < 8; i++) S += sm[i][lane];
        int row = r0 + lane;
        if (row < N) {
            float t = g_tgt[row];
            t = fminf(1.f, fmaxf(-1.f, t));
            float st = sqrtf(fmaxf(0.f, 1.f - t * t));
            float cm = t * cosM - st * sinM;
            // swap the (deg-3 approximated) raw target term for the exact margin term
            S += expf(cm - 1.f) - expv3(t);
            S = fmaxf(S, 1e-30f);
            g_rowloss[row] = (1.f + logf(S)) - cm;
        }
    }
}

__global__ void k_reduce(float* __restrict__ out, int N) {
    __shared__ float red[8];
    float s = 0.f;
    for (int i = threadIdx.x; i < N; i += blockDim.x) s += g_rowloss[i];
    #pragma unroll
    for (int m = 16; m; m >>= 1) s += __shfl_xor_sync(0xffffffffu, s, m);
    if ((threadIdx.x & 31) == 0) red[threadIdx.x >> 5] = s;
    __syncthreads();
    if (threadIdx.x < 32) {
        float v = (threadIdx.x < (blockDim.x >> 5)) ? red[threadIdx.x] : 0.f;
        #pragma unroll
        for (int m = 16; m; m >>= 1) v += __shfl_xor_sync(0xffffffffu, v, m);
        if (threadIdx.x == 0) out[0] = v / (float)N;
    }
}

extern "C" void kernel_launch(void* const* d_in, const int* in_sizes, int n_in,
                              void* d_out, int out_size) {
    const float* x   = (const float*)d_in[0];
    const int*   lab = (const int*)d_in[1];
    const float* w   = (const float*)d_in[2];
    int N = in_sizes[0] / EDIM;
    int C = in_sizes[2] / EDIM;
    int ncb = (C + 255) >> 8;

    cudaFuncSetAttribute(k_lse_mma, cudaFuncAttributeMaxDynamicSharedMemorySize, SM_TOT);

    k_norm_rows<<<(N + 7) / 8, 256>>>(x, N, 0);
    k_norm_rows<<<(C + 7) / 8, 256>>>(w, C, 1);
    k_prep_labels<<<1, 256>>>(lab, N);
    k_lse_mma<<<NPERS, 288, SM_TOT>>>(N, C);       // launch #4 -> ncu's profiled slot
    k_target_dot<<<N, 128>>>();

    float cM = (float)cos(4.0);   // MARGIN = 4 rad
    float sM = (float)sin(4.0);
    k_combine<<<(N + 31) / 32, 256>>>(N, ncb * NSUB, cM, sM);
    k_reduce<<<1, 256>>>((float*)d_out, N);
}

// round 17
// speedup vs baseline: 1.5515x; 1.5515x over previous
#include <cuda_runtime.h>
#include <cuda_bf16.h>
#include <math.h>
#include <stdint.h>

// Fixed dataset shapes
#define MAX_N 4096
#define MAX_C 50257
#define EDIM  512
#define NCB   197          // ceil(50257 / 256) class blocks
#define NSUB  4            // per-warp_n partial sums per class block

// ---------------- device scratch (no allocations allowed) ----------------
__device__ __nv_bfloat16 g_xb[MAX_N * EDIM];     // normalized x, bf16
__device__ __nv_bfloat16 g_wb[(size_t)MAX_C * EDIM]; // normalized W, bf16 (~51.5 MB)
__device__ int   g_label[MAX_N];
__device__ float g_tgt[MAX_N];
__device__ float g_partS[(size_t)NCB * NSUB * MAX_N];  // [cb*4+wn][row] partial sums
__device__ float g_rowloss[MAX_N];

// ---------------- PTX helpers (sm_80-class + base-sm_100 f32x2; no 'a' gating) --------
__device__ __forceinline__ uint32_t smem_u32(const void* p) {
    return (uint32_t)__cvta_generic_to_shared(p);
}
__device__ __forceinline__ void cp_async16(uint32_t saddr, const void* gaddr, int srcsz) {
    asm volatile("cp.async.cg.shared.global [%0], [%1], 16, %2;\n"
                 :: "r"(saddr), "l"(gaddr), "r"(srcsz) : "memory");
}
__device__ __forceinline__ void cp_commit() { asm volatile("cp.async.commit_group;\n" ::: "memory"); }
template <int n>
__device__ __forceinline__ void cp_wait_group() {
    asm volatile("cp.async.wait_group %0;\n" :: "n"(n) : "memory");
}
__device__ __forceinline__ void ldsm_x4(uint32_t& r0, uint32_t& r1, uint32_t& r2, uint32_t& r3,
                                        uint32_t addr) {
    asm volatile("ldmatrix.sync.aligned.m8n8.x4.shared.b16 {%0,%1,%2,%3}, [%4];"
                 : "=r"(r0), "=r"(r1), "=r"(r2), "=r"(r3) : "r"(addr));
}
__device__ __forceinline__ void mma16816(float* c, uint32_t a0, uint32_t a1, uint32_t a2,
                                         uint32_t a3, uint32_t b0, uint32_t b1) {
    asm volatile("mma.sync.aligned.m16n8k16.row.col.f32.bf16.bf16.f32 "
                 "{%0,%1,%2,%3}, {%4,%5,%6,%7}, {%8,%9}, {%0,%1,%2,%3};"
                 : "+f"(c[0]), "+f"(c[1]), "+f"(c[2]), "+f"(c[3])
                 : "r"(a0), "r"(a1), "r"(a2), "r"(a3), "r"(b0), "r"(b1));
}
__device__ __forceinline__ uint32_t sw128(uint32_t b) { return b ^ ((b >> 3) & 0x70); }

// packed f32x2 (PTX ISA 8.6, sm_100+ base feature)
__device__ __forceinline__ uint64_t f2pack(float x, float y) {
    uint64_t r;
    asm("mov.b64 %0, {%1, %2};" : "=l"(r) : "r"(__float_as_uint(x)), "r"(__float_as_uint(y)));
    return r;
}
__device__ __forceinline__ float f2sum(uint64_t v) {
    uint32_t a, b;
    asm("mov.b64 {%0, %1}, %2;" : "=r"(a), "=r"(b) : "l"(v));
    return __uint_as_float(a) + __uint_as_float(b);
}
__device__ __forceinline__ uint64_t fma2(uint64_t a, uint64_t b, uint64_t c) {
    uint64_t d;
    asm("fma.rn.f32x2 %0, %1, %2, %3;" : "=l"(d) : "l"(a), "l"(b), "l"(c));
    return d;
}
__device__ __forceinline__ uint64_t add2(uint64_t a, uint64_t b) {
    uint64_t d;
    asm("add.rn.f32x2 %0, %1, %2;" : "=l"(d) : "l"(a), "l"(b));
    return d;
}

// exp(v-1) deg-3 Taylor, coeffs e^-1 * {1, 1, 1/2, 1/6}.
#define EC0 3.6787944117144233e-1f
#define EC1 3.6787944117144233e-1f
#define EC2 1.8393972058572117e-1f
#define EC3 6.1313240195240389e-2f
__device__ __forceinline__ float expv3(float v) {
    float p = EC3;
    p = fmaf(p, v, EC2); p = fmaf(p, v, EC1); p = fmaf(p, v, EC0);
    return p;
}

// ---------------- fused normalization: x AND W in one launch (warp per row) ----------
__global__ void k_norm_all(const float* __restrict__ x, const float* __restrict__ w,
                           int N, int C) {
    int row = blockIdx.x * (blockDim.x >> 5) + (threadIdx.x >> 5);
    const float* src;
    __nv_bfloat16* dst;
    int r;
    if (row < N) { src = x; dst = g_xb; r = row; }
    else {
        r = row - N;
        if (r >= C) return;
        src = w; dst = g_wb;
    }
    int lane = threadIdx.x & 31;
    const float4* ip = reinterpret_cast<const float4*>(src) + (size_t)r * (EDIM >> 2);
    float4 v[4];
    float ss = 0.f;
    #pragma unroll
    for (int q = 0; q < 4; q++) {
        v[q] = ip[lane + 32 * q];
        ss += v[q].x * v[q].x + v[q].y * v[q].y + v[q].z * v[q].z + v[q].w * v[q].w;
    }
    #pragma unroll
    for (int m = 16; m; m >>= 1) ss += __shfl_xor_sync(0xffffffffu, ss, m);
    float scale = 1.f / fmaxf(sqrtf(ss), 1e-12f);
    __nv_bfloat162* op = reinterpret_cast<__nv_bfloat162*>(dst) + (size_t)r * (EDIM >> 1);
    #pragma unroll
    for (int q = 0; q < 4; q++) {
        int i = lane + 32 * q;
        op[2 * i]     = __floats2bfloat162_rn(v[q].x * scale, v[q].y * scale);
        op[2 * i + 1] = __floats2bfloat162_rn(v[q].z * scale, v[q].w * scale);
    }
}

// ---------------- label dtype detection (int32 vs int64 storage) ----------------
__global__ void k_prep_labels(const int* __restrict__ li, int N) {
    int any = 0;
    for (int i = threadIdx.x; i < (N >> 1); i += blockDim.x)
        if (li[2 * i + 1] != 0) any = 1;
    int is32 = __syncthreads_or(any);
    if (is32) { for (int i = threadIdx.x; i < N; i += blockDim.x) g_label[i] = li[i]; }
    else      { for (int i = threadIdx.x; i < N; i += blockDim.x) g_label[i] = li[2 * i]; }
}

// ---------------- target cosine per row (warp per row; bf16 in, fp32 accumulate) ------
__device__ __forceinline__ float dotb2(uint32_t ua, uint32_t ub) {
    float2 fa = __bfloat1622float2(*reinterpret_cast<__nv_bfloat162*>(&ua));
    float2 fb = __bfloat1622float2(*reinterpret_cast<__nv_bfloat162*>(&ub));
    return fa.x * fb.x + fa.y * fb.y;
}
__global__ void k_target_dot(int N) {
    int row = blockIdx.x * 8 + (threadIdx.x >> 5);
    if (row >= N) return;
    int lane = threadIdx.x & 31;
    int lab = g_label[row];
    const uint4* a = reinterpret_cast<const uint4*>(g_xb + (size_t)row * EDIM);
    const uint4* b = reinterpret_cast<const uint4*>(g_wb + (size_t)lab * EDIM);
    float s = 0.f;
    #pragma unroll
    for (int q = 0; q < 2; q++) {             // 64 uint4 per row / 32 lanes
        uint4 ua = a[lane + 32 * q];
        uint4 ub = b[lane + 32 * q];
        s += dotb2(ua.x, ub.x) + dotb2(ua.y, ub.y) + dotb2(ua.z, ub.z) + dotb2(ua.w, ub.w);
    }
    #pragma unroll
    for (int m = 16; m; m >>= 1) s += __shfl_xor_sync(0xffffffffu, s, m);
    if (lane == 0) g_tgt[row] = s;
}

// ---------------- persistent bf16 HMMA GEMM + fused sum-exp (barrier-free epilogue) ----
// Grid 148 (1 CTA/SM). Block 256 = 8 warps (2m x 4n), warp subtile 64x64.
// SMEM: A resident [8 chunks][128 rows][128B] = 128KB @0,
//       B ring 3 stages x [256 rows][128B] = 96KB @131072. No srow exchange.
#define SM_B    131072
#define SM_TOT  229376
#define NPERS   148

__device__ __forceinline__ void load_A(uint32_t sb, int rb, int tid) {
    const __nv_bfloat16* ag = g_xb + ((size_t)rb * 128) * EDIM;
    for (int q = 0; q < 32; q++) {            // 8192 16B chunks
        int i = tid + q * 256;
        int kc = i >> 10, j = i & 1023;
        int row = j >> 3, s16 = j & 7;
        cp_async16(sb + kc * 16384 + sw128(row * 128 + s16 * 16),
                   ag + (size_t)row * EDIM + kc * 64 + s16 * 8, 16);
    }
}
__device__ __forceinline__ void load_B(uint32_t sb, int stage, int cb, int kb, int C, int tid) {
    uint32_t bbase = sb + SM_B + stage * 32768;
    #pragma unroll
    for (int q = 0; q < 8; q++) {             // 2048 16B chunks
        int i = tid + q * 256;
        int row = i >> 3, s16 = i & 7;
        int cls = cb * 256 + row;
        int ok = (cls < C);
        cp_async16(bbase + sw128(row * 128 + s16 * 16),
                   g_wb + (size_t)(ok ? cls : 0) * EDIM + kb * 64 + s16 * 8, ok ? 16 : 0);
    }
}

__global__ void __launch_bounds__(256, 1) k_lse_mma(int N, int C) {
    extern __shared__ __align__(128) char smem[];
    const uint32_t sb = smem_u32(smem);
    const int tid  = threadIdx.x;
    const int warp = tid >> 5;
    const int lane = tid & 31;
    const int warp_m = warp >> 2;       // 0..1
    const int warp_n = warp & 3;        // 0..3

    const int nrb = N >> 7;
    const int ncb = (C + 255) >> 8;
    const int tot = nrb * ncb;
    int ts = (int)(((long long)blockIdx.x * tot) / NPERS);
    int te = (int)(((long long)(blockIdx.x + 1) * tot) / NPERS);

    // ldmatrix lane geometry
    const int lrow = (lane & 7) + ((lane >> 3) & 1) * 8;
    const int lkb  = ((lane >> 4) & 1) * 16;
    const int arow = warp_m * 64 + lrow;
    const int brow = warp_n * 64 + lrow;

    float acc[4][8][4];

    int t = ts;
    while (t < te) {
        int rb = t / ncb;
        int segEnd = min(te, (rb + 1) * ncb);
        int L = (segEnd - t) * 8;

        load_A(sb, rb, tid); cp_commit();
        load_B(sb, 0, t % ncb, 0, C, tid); cp_commit();
        load_B(sb, 1, t % ncb, 1, C, tid); cp_commit();

        for (int j = 0; j < L; j++) {
            int kb = j & 7;
            cp_wait_group<1>(); __syncthreads();
            // prefetch j+2 AFTER the barrier (stage (j+2)%3 was consumed at iter j-1)
            if (j + 2 < L) {
                int nj = j + 2;
                load_B(sb, nj % 3, (t + (nj >> 3)) % ncb, nj & 7, C, tid);
            }
            cp_commit();

            if (kb == 0) {
                #pragma unroll
                for (int mf = 0; mf < 4; mf++)
                    #pragma unroll
                    for (int nf = 0; nf < 8; nf++)
                        #pragma unroll
                        for (int q = 0; q < 4; q++) acc[mf][nf][q] = 0.f;
            }

            uint32_t abase = sb + kb * 16384;
            uint32_t bbase = sb + SM_B + (j % 3) * 32768;
            #pragma unroll
            for (int kf = 0; kf < 4; kf++) {
                uint32_t a[4][4];
                #pragma unroll
                for (int mf = 0; mf < 4; mf++)
                    ldsm_x4(a[mf][0], a[mf][1], a[mf][2], a[mf][3],
                            abase + sw128((arow + mf * 16) * 128 + kf * 32 + lkb));
                uint32_t b[8][2];
                #pragma unroll
                for (int np = 0; np < 4; np++) {
                    uint32_t r0, r1, r2, r3;
                    ldsm_x4(r0, r1, r2, r3,
                            bbase + sw128((brow + np * 16) * 128 + kf * 32 + lkb));
                    b[np * 2][0] = r0; b[np * 2 + 1][0] = r1;
                    b[np * 2][1] = r2; b[np * 2 + 1][1] = r3;
                }
                #pragma unroll
                for (int mf = 0; mf < 4; mf++)
                    #pragma unroll
                    for (int nf = 0; nf < 8; nf++)
                        mma16816(acc[mf][nf], a[mf][0], a[mf][1], a[mf][2], a[mf][3],
                                 b[nf][0], b[nf][1]);
            }

            if (kb == 7) {
                // ---- barrier-free epilogue: per-warp_n partial sums straight to global ----
                int ct = t + (j >> 3);
                int cb = ct % ncb;
                float rs[8];
                const bool full = (cb * 256 + 256) <= C;
                if (full) {
                    uint64_t c3 = f2pack(EC3, EC3), c2 = f2pack(EC2, EC2),
                             c1 = f2pack(EC1, EC1), c0 = f2pack(EC0, EC0);
                    uint64_t rp[8];
                    #pragma unroll
                    for (int i = 0; i < 8; i++) rp[i] = 0;   // (0.0f, 0.0f)
                    #pragma unroll
                    for (int mf = 0; mf < 4; mf++) {
                        #pragma unroll
                        for (int nf = 0; nf < 8; nf++) {
                            float* c = acc[mf][nf];
                            #pragma unroll
                            for (int h = 0; h < 2; h++) {
                                uint64_t v = f2pack(c[2 * h], c[2 * h + 1]);
                                uint64_t p = c3;
                                p = fma2(p, v, c2); p = fma2(p, v, c1); p = fma2(p, v, c0);
                                rp[mf * 2 + h] = add2(rp[mf * 2 + h], p);
                            }
                        }
                    }
                    #pragma unroll
                    for (int i = 0; i < 8; i++) rs[i] = f2sum(rp[i]);
                } else {
                    #pragma unroll
                    for (int i = 0; i < 8; i++) rs[i] = 0.f;
                    const int colb = cb * 256 + warp_n * 64 + (lane & 3) * 2;
                    #pragma unroll
                    for (int mf = 0; mf < 4; mf++)
                        #pragma unroll
                        for (int nf = 0; nf < 8; nf++) {
                            float* c = acc[mf][nf];
                            int cc = colb + nf * 8;
                            if (cc < C)     { rs[mf * 2] += expv3(c[0]); rs[mf * 2 + 1] += expv3(c[2]); }
                            if (cc + 1 < C) { rs[mf * 2] += expv3(c[1]); rs[mf * 2 + 1] += expv3(c[3]); }
                        }
                }
                #pragma unroll
                for (int i = 0; i < 8; i++) {
                    rs[i] += __shfl_xor_sync(0xffffffffu, rs[i], 1);
                    rs[i] += __shfl_xor_sync(0xffffffffu, rs[i], 2);
                }
                if ((lane & 3) == 0) {
                    float* dst = g_partS + ((size_t)cb * NSUB + warp_n) * MAX_N + rb * 128;
                    #pragma unroll
                    for (int mf = 0; mf < 4; mf++) {
                        int r = warp_m * 64 + mf * 16 + (lane >> 2);
                        dst[r]     = rs[mf * 2];
                        dst[r + 8] = rs[mf * 2 + 1];
                    }
                }
                // no barrier needed: epilogue touches only registers + global
            }
        }
        cp_wait_group<0>(); __syncthreads();   // drain before A reload / exit
        t = segEnd;
    }
}

// ---------------- combine partials (cooperative, coalesced) + margin patch ------------
__global__ void k_combine(int N, int nn, float cosM, float sinM) {
    int r0 = blockIdx.x * 32;
    int lane = threadIdx.x & 31;
    int w = threadIdx.x >> 5;
    const float* __restrict__ p = g_partS + r0 + lane;
    float s = 0.f;
    int sIdx = w;
    #pragma unroll 4
    for (; sIdx < nn; sIdx += 8) s += p[(size_t)sIdx * MAX_N];
    __shared__ float sm[8][32];
    sm[w][lane] = s;
    __syncthreads();
    if (w == 0) {
        float S = 0.f;
        #pragma unroll
        for (int i = 0; i < 8; i++) S += sm[i][lane];
        int row = r0 + lane;
        if (row < N) {
            float t = g_tgt[row];
            t = fminf(1.f, fmaxf(-1.f, t));
            float st = sqrtf(fmaxf(0.f, 1.f - t * t));
            float cm = t * cosM - st * sinM;
            // swap the (deg-3 approximated) raw target term for the exact margin term
            S += expf(cm - 1.f) - expv3(t);
            S = fmaxf(S, 1e-30f);
            g_rowloss[row] = (1.f + logf(S)) - cm;
        }
    }
}

__global__ void k_reduce(float* __restrict__ out, int N) {
    __shared__ float red[8];
    float s = 0.f;
    for (int i = threadIdx.x; i < N; i += blockDim.x) s += g_rowloss[i];
    #pragma unroll
    for (int m = 16; m; m >>= 1) s += __shfl_xor_sync(0xffffffffu, s, m);
    if ((threadIdx.x & 31) == 0) red[threadIdx.x >> 5] = s;
    __syncthreads();
    if (threadIdx.x < 32) {
        float v = (threadIdx.x < (blockDim.x >> 5)) ? red[threadIdx.x] : 0.f;
        #pragma unroll
        for (int m = 16; m; m >>= 1) v += __shfl_xor_sync(0xffffffffu, v, m);
        if (threadIdx.x == 0) out[0] = v / (float)N;
    }
}

extern "C" void kernel_launch(void* const* d_in, const int* in_sizes, int n_in,
                              void* d_out, int out_size) {
    const float* x   = (const float*)d_in[0];
    const int*   lab = (const int*)d_in[1];
    const float* w   = (const float*)d_in[2];
    int N = in_sizes[0] / EDIM;
    int C = in_sizes[2] / EDIM;
    int ncb = (C + 255) >> 8;

    cudaFuncSetAttribute(k_lse_mma, cudaFuncAttributeMaxDynamicSharedMemorySize, SM_TOT);

    k_norm_all<<<(N + C + 7) / 8, 256>>>(x, w, N, C);
    k_prep_labels<<<1, 256>>>(lab, N);
    k_target_dot<<<(N + 7) / 8, 256>>>(N);
    k_lse_mma<<<NPERS, 256, SM_TOT>>>(N, C);       // launch #4 -> ncu's profiled slot

    float cM = (float)cos(4.0);   // MARGIN = 4 rad
    float sM = (float)sin(4.0);
    k_combine<<<(N + 31) / 32, 256>>>(N, ncb * NSUB, cM, sM);
    k_reduce<<<1, 256>>>((float*)d_out, N);
}